// round 1
// baseline (speedup 1.0000x reference)
#include <cuda_runtime.h>

// Circuit (fully unrolled from the reference DAG):
//   data0 = l0             data1 = l1            data2 = log1p(-exp(l2))
//   data3 = log1p(-exp(l1)) data4 = l2           data6 = log1p(-exp(l0))
//   data5 = LSE(data1+data2, data3+data4)
//   data7 = LSE(data1+data4, -2000)  == data1+data4 exactly in fp32
//   data8 = LSE(data0+data5, data6+data7)   -> output
//
// Pure elementwise: 3 floats in, 1 float out, per batch element.

__device__ __forceinline__ float lse2(float a, float b) {
    float m = fmaxf(a, b);
    float d = fminf(a, b) - m;           // d <= 0
    return m + log1pf(__expf(d));        // exp(d) in (0,1], log1pf accurate
}

__device__ __forceinline__ float circuit_eval(float l0, float l1, float l2) {
    // q_v = log(1 - p_v) in log space
    float q0 = log1pf(-__expf(l0));
    float q1 = log1pf(-__expf(l1));
    float q2 = log1pf(-__expf(l2));

    float d5 = lse2(l1 + q2, q1 + l2);
    float d7 = l1 + l2;                  // LSE(l1+l2, -2000): second term exp-underflows to 0
    return lse2(l0 + d5, q0 + d7);       // d8
}

__global__ void __launch_bounds__(256)
circuit_kernel(const float4* __restrict__ in, float4* __restrict__ out, int n4) {
    int i = blockIdx.x * blockDim.x + threadIdx.x;
    if (i >= n4) return;

    // 4 batch elements = 12 floats = 3 float4 loads (row-major (B,3) input)
    float4 a = in[3 * i + 0];
    float4 b = in[3 * i + 1];
    float4 c = in[3 * i + 2];

    float4 r;
    r.x = circuit_eval(a.x, a.y, a.z);
    r.y = circuit_eval(a.w, b.x, b.y);
    r.z = circuit_eval(b.z, b.w, c.x);
    r.w = circuit_eval(c.y, c.z, c.w);

    out[i] = r;
}

// Tail handler for batch sizes not divisible by 4 (not hit for B=4194304,
// but keeps the kernel correct for any shape).
__global__ void circuit_tail_kernel(const float* __restrict__ in,
                                    float* __restrict__ out,
                                    int start, int n) {
    int i = start + blockIdx.x * blockDim.x + threadIdx.x;
    if (i >= n) return;
    out[i] = circuit_eval(in[3 * i + 0], in[3 * i + 1], in[3 * i + 2]);
}

extern "C" void kernel_launch(void* const* d_in, const int* in_sizes, int n_in,
                              void* d_out, int out_size) {
    const float* log_probs = (const float*)d_in[0];
    float* out = (float*)d_out;

    int B = out_size;            // output is (1, B) floats
    int n4 = B / 4;

    if (n4 > 0) {
        int threads = 256;
        int blocks = (n4 + threads - 1) / threads;
        circuit_kernel<<<blocks, threads>>>(
            (const float4*)log_probs, (float4*)out, n4);
    }
    int rem_start = n4 * 4;
    if (rem_start < B) {
        int rem = B - rem_start;
        circuit_tail_kernel<<<(rem + 255) / 256, 256>>>(log_probs, out, rem_start, B);
    }
}

// round 2
// speedup vs baseline: 1.7171x; 1.7171x over previous
#include <cuda_runtime.h>

// Circuit evaluated in LINEAR probability space (one log at the end):
//   p_v = exp(l_v)
//   s   = p1*(1-p2) + (1-p1)*p2     (node 5, linearized)
//   t   = p1*p2                     (node 7; the -2000 disjunct is exactly 0)
//   x   = p0*s + (1-p0)*t           (node 8)
//   out = log(x)
// Identical math to the nested logsumexp reference; all terms positive,
// x >= ~2.5e-3 for p in [0.05,0.95], so no cancellation / log-domain issues.
// Per element: 3x MUFU.EX2 + 1x MUFU.LG2 + ~7 FMA ops (vs ~100+ before).

__device__ __forceinline__ float circuit_eval(float l0, float l1, float l2) {
    float p0 = __expf(l0);
    float p1 = __expf(l1);
    float p2 = __expf(l2);

    float t  = p1 * p2;
    float a  = __fmaf_rn(-p1, p2, p1);    // p1*(1-p2)  (exact-ish, no cancellation)
    float b  = __fmaf_rn(-p1, p2, p2);    // (1-p1)*p2
    float s  = a + b;

    float q0 = 1.0f - p0;
    float x  = __fmaf_rn(p0, s, q0 * t);  // p0*s + (1-p0)*t, both terms positive
    return __logf(x);
}

__global__ void __launch_bounds__(256)
circuit_kernel(const float4* __restrict__ in, float4* __restrict__ out, int n8) {
    int i = blockIdx.x * blockDim.x + threadIdx.x;
    if (i >= n8) return;

    // 8 batch elements = 24 floats = 6 float4 loads; issue all loads up front (MLP=6)
    const float4* p = in + 6 * (size_t)i;
    float4 v0 = p[0];
    float4 v1 = p[1];
    float4 v2 = p[2];
    float4 v3 = p[3];
    float4 v4 = p[4];
    float4 v5 = p[5];

    float4 r0, r1;
    r0.x = circuit_eval(v0.x, v0.y, v0.z);
    r0.y = circuit_eval(v0.w, v1.x, v1.y);
    r0.z = circuit_eval(v1.z, v1.w, v2.x);
    r0.w = circuit_eval(v2.y, v2.z, v2.w);
    r1.x = circuit_eval(v3.x, v3.y, v3.z);
    r1.y = circuit_eval(v3.w, v4.x, v4.y);
    r1.z = circuit_eval(v4.z, v4.w, v5.x);
    r1.w = circuit_eval(v5.y, v5.z, v5.w);

    out[2 * (size_t)i + 0] = r0;
    out[2 * (size_t)i + 1] = r1;
}

// Tail for B not divisible by 8 (not hit for B=4194304).
__global__ void circuit_tail_kernel(const float* __restrict__ in,
                                    float* __restrict__ out,
                                    int start, int n) {
    int i = start + blockIdx.x * blockDim.x + threadIdx.x;
    if (i >= n) return;
    out[i] = circuit_eval(in[3 * i + 0], in[3 * i + 1], in[3 * i + 2]);
}

extern "C" void kernel_launch(void* const* d_in, const int* in_sizes, int n_in,
                              void* d_out, int out_size) {
    const float* log_probs = (const float*)d_in[0];
    float* out = (float*)d_out;

    int B = out_size;            // output is (1, B) floats
    int n8 = B / 8;

    if (n8 > 0) {
        int threads = 256;
        int blocks = (n8 + threads - 1) / threads;
        circuit_kernel<<<blocks, threads>>>(
            (const float4*)log_probs, (float4*)out, n8);
    }
    int rem_start = n8 * 8;
    if (rem_start < B) {
        int rem = B - rem_start;
        circuit_tail_kernel<<<(rem + 255) / 256, 256>>>(log_probs, out, rem_start, B);
    }
}

// round 3
// speedup vs baseline: 2.2828x; 1.3294x over previous
#include <cuda_runtime.h>

// Circuit in linear probability space (one log at the end):
//   p_v = exp(l_v);  s = p1(1-p2) + (1-p1)p2;  t = p1*p2
//   out = log(p0*s + (1-p0)*t)
// Identical to the reference's nested logsumexp (slot-9's -1000 disjunct
// exp-underflows to exactly 0 there too).
__device__ __forceinline__ float circuit_eval(float l0, float l1, float l2) {
    float p0 = __expf(l0);
    float p1 = __expf(l1);
    float p2 = __expf(l2);

    float t  = p1 * p2;
    float a  = __fmaf_rn(-p1, p2, p1);    // p1*(1-p2)
    float b  = __fmaf_rn(-p1, p2, p2);    // (1-p1)*p2
    float s  = a + b;

    float q0 = 1.0f - p0;
    float x  = __fmaf_rn(p0, s, q0 * t);
    return __logf(x);
}

// Warp tile: 128 elements = 96 float4 in, 32 float4 out.
// Stage coalesced global loads through smem so each lane then owns 4
// complete elements (3 consecutive float4), and the store is coalesced.
static constexpr int WARPS_PER_BLOCK = 8;
static constexpr int THREADS = WARPS_PER_BLOCK * 32;

__global__ void __launch_bounds__(THREADS)
circuit_kernel(const float4* __restrict__ in, float4* __restrict__ out,
               int n_warptiles) {
    __shared__ float4 tile[WARPS_PER_BLOCK][96];

    int warp = threadIdx.x >> 5;
    int lane = threadIdx.x & 31;
    int wgid = blockIdx.x * WARPS_PER_BLOCK + warp;
    if (wgid >= n_warptiles) return;

    // Coalesced loads: instruction k covers a contiguous 512B across the warp.
    const float4* pin = in + (size_t)wgid * 96;
    float4 a = pin[lane];
    float4 b = pin[32 + lane];
    float4 c = pin[64 + lane];

    // Stage (STS.128, contiguous -> conflict-free)
    tile[warp][lane]      = a;
    tile[warp][32 + lane] = b;
    tile[warp][64 + lane] = c;
    __syncwarp();

    // Each lane reads its own 3 consecutive float4 = 4 complete elements.
    // LDS.128 at 48B lane stride: banks {12t..12t+3 mod 32} -> conflict-free.
    float4 v0 = tile[warp][3 * lane + 0];
    float4 v1 = tile[warp][3 * lane + 1];
    float4 v2 = tile[warp][3 * lane + 2];

    float4 r;
    r.x = circuit_eval(v0.x, v0.y, v0.z);
    r.y = circuit_eval(v0.w, v1.x, v1.y);
    r.z = circuit_eval(v1.z, v1.w, v2.x);
    r.w = circuit_eval(v2.y, v2.z, v2.w);

    // Coalesced store: contiguous 512B across the warp.
    out[(size_t)wgid * 32 + lane] = r;
}

// Tail for elements beyond the last full warp tile (not hit for B=4194304).
__global__ void circuit_tail_kernel(const float* __restrict__ in,
                                    float* __restrict__ out,
                                    int start, int n) {
    int i = start + blockIdx.x * blockDim.x + threadIdx.x;
    if (i >= n) return;
    out[i] = circuit_eval(in[3 * i + 0], in[3 * i + 1], in[3 * i + 2]);
}

extern "C" void kernel_launch(void* const* d_in, const int* in_sizes, int n_in,
                              void* d_out, int out_size) {
    const float* log_probs = (const float*)d_in[0];
    float* out = (float*)d_out;

    int B = out_size;                       // output is (1, B) floats
    int n_warptiles = B / 128;              // 128 elements per warp tile

    if (n_warptiles > 0) {
        int blocks = (n_warptiles + WARPS_PER_BLOCK - 1) / WARPS_PER_BLOCK;
        circuit_kernel<<<blocks, THREADS>>>(
            (const float4*)log_probs, (float4*)out, n_warptiles);
    }
    int done = n_warptiles * 128;
    if (done < B) {
        int rem = B - done;
        circuit_tail_kernel<<<(rem + 255) / 256, 256>>>(log_probs, out, done, B);
    }
}